// round 2
// baseline (speedup 1.0000x reference)
#include <cuda_runtime.h>
#include <math.h>
#include <stdint.h>

#define N_NODES 200000
#define N_EVENTS 50000
#define MEMD 128
#define TWO_E (2 * N_EVENTS)

// ---------------- scratch (static device globals; no runtime allocation) ----
__device__ int      g_last_pos[N_NODES];
__device__ int      g_sel[TWO_E];
__device__ int      g_count;
__device__ float    g_mem_new[(size_t)N_NODES * MEMD];
__device__ float    g_lu_new[N_NODES];
__device__ float    g_G[(size_t)TWO_E * 512];          // GRU pre-gate outputs
__device__ float    g_kv[(size_t)N_EVENTS * 256];      // per-edge k (0:128) and v (128:256)
__device__ float    g_logit[N_EVENTS * 2];
__device__ float    g_aexp[N_EVENTS * 2];
__device__ unsigned g_mx[N_NODES * 2];                 // order-preserving encoded max logit
__device__ float    g_denom[N_NODES * 2];
__device__ float    g_z[(size_t)N_NODES * MEMD];       // skip + attention out

// order-preserving float<->uint encoding for atomicMax on floats
__device__ __forceinline__ unsigned enc_f(float x) {
    unsigned u = __float_as_uint(x);
    return (u & 0x80000000u) ? ~u : (u | 0x80000000u);
}
__device__ __forceinline__ float dec_f(unsigned u) {
    unsigned v = (u & 0x80000000u) ? (u & 0x7FFFFFFFu) : ~u;
    return __uint_as_float(v);
}
__device__ __forceinline__ float sigmoidf_(float x) { return 1.f / (1.f + expf(-x)); }

// ---------------- init / copy / last-pos / compact ---------------------------
__global__ void k_init() {
    int i = blockIdx.x * blockDim.x + threadIdx.x;
    if (i < N_NODES) g_last_pos[i] = -1;
    if (i < 2 * N_NODES) { g_mx[i] = 0u; g_denom[i] = 0.f; }
    if (i == 0) g_count = 0;
}

__global__ void k_copy(const float4* __restrict__ mem, const float* __restrict__ lu) {
    int i = blockIdx.x * blockDim.x + threadIdx.x;
    if (i < N_NODES * (MEMD / 4)) ((float4*)g_mem_new)[i] = mem[i];
    if (i < N_NODES) g_lu_new[i] = lu[i];
}

__global__ void k_lastpos(const int* __restrict__ src, const int* __restrict__ dst) {
    int j = blockIdx.x * blockDim.x + threadIdx.x;
    if (j >= TWO_E) return;
    int id = (j < N_EVENTS) ? src[j] : dst[j - N_EVENTS];
    atomicMax(&g_last_pos[id], j);
}

__global__ void k_compact(const int* __restrict__ src, const int* __restrict__ dst) {
    int j = blockIdx.x * blockDim.x + threadIdx.x;
    if (j >= TWO_E) return;
    int id = (j < N_EVENTS) ? src[j] : dst[j - N_EVENTS];
    if (g_last_pos[id] == j) {
        int p = atomicAdd(&g_count, 1);
        g_sel[p] = j;
    }
}

// ---------------- GRU GEMM: G[m][0:512] = x'(512) @ W'(512x512)^T -------------
// x' = [mem[id](128) | mem[other](128) | msg(64) | timeenc(64) | mem[id](128)]
// rows of W': [Wih_r|Whh_r], [Wih_z|Whh_z], [Wih_n|0], [0|Whh_n]
__global__ __launch_bounds__(256) void k_gru_gemm(
    const float* __restrict__ memory, const float* __restrict__ last_update,
    const float* __restrict__ t, const float* __restrict__ msg,
    const int* __restrict__ src, const int* __restrict__ dst,
    const float* __restrict__ time_w, const float* __restrict__ time_b,
    const float* __restrict__ Wih, const float* __restrict__ Whh)
{
    const int count = g_count;
    const int m0 = blockIdx.x * 64;
    if (m0 >= count) return;
    const int bn0 = blockIdx.y * 64;
    const int tid = threadIdx.x;

    __shared__ int   s_id[64], s_oth[64], s_e[64];
    __shared__ float s_dt[64];
    __shared__ float As[16][68];
    __shared__ float Bs[16][68];

    if (tid < 64) {
        int mm = min(m0 + tid, count - 1);
        int j = g_sel[mm];
        int e  = (j < N_EVENTS) ? j : j - N_EVENTS;
        int id = (j < N_EVENTS) ? src[e] : dst[e];
        int ot = (j < N_EVENTS) ? dst[e] : src[e];
        s_id[tid] = id; s_oth[tid] = ot; s_e[tid] = e;
        s_dt[tid] = t[e] - last_update[id];
    }
    __syncthreads();

    float acc[4][4];
#pragma unroll
    for (int i = 0; i < 4; i++)
#pragma unroll
        for (int j = 0; j < 4; j++) acc[i][j] = 0.f;

    const int tm0 = (tid & 15) * 4;
    const int tn0 = (tid >> 4) * 4;

    for (int k0 = 0; k0 < 512; k0 += 16) {
        // stage A (gathered), 4 elems/thread
#pragma unroll
        for (int s = 0; s < 4; s++) {
            int idx = tid + s * 256;
            int kk = idx & 15, m = idx >> 4;
            int k = k0 + kk;
            float v;
            if (k < 128)       v = memory[(size_t)s_id[m] * 128 + k];
            else if (k < 256)  v = memory[(size_t)s_oth[m] * 128 + (k - 128)];
            else if (k < 320)  v = msg[(size_t)s_e[m] * 64 + (k - 256)];
            else if (k < 384)  v = cosf(fmaf(s_dt[m], time_w[k - 320], time_b[k - 320]));
            else               v = memory[(size_t)s_id[m] * 128 + (k - 384)];
            As[kk][m] = v;
        }
        // stage B (virtual weight), 4 elems/thread
#pragma unroll
        for (int s = 0; s < 4; s++) {
            int idx = tid + s * 256;
            int kk = idx & 15, n = idx >> 4;
            int k = k0 + kk;
            int o = bn0 + n;
            int g = o >> 7, r = o & 127;
            float v;
            if (g < 2)       v = (k < 384) ? Wih[(size_t)(g * 128 + r) * 384 + k]
                                           : Whh[(size_t)(g * 128 + r) * 128 + (k - 384)];
            else if (g == 2) v = (k < 384) ? Wih[(size_t)(256 + r) * 384 + k] : 0.f;
            else             v = (k >= 384) ? Whh[(size_t)(256 + r) * 128 + (k - 384)] : 0.f;
            Bs[kk][n] = v;
        }
        __syncthreads();
#pragma unroll
        for (int kk = 0; kk < 16; kk++) {
            float4 a = *(const float4*)&As[kk][tm0];
            float4 b = *(const float4*)&Bs[kk][tn0];
            float av[4] = {a.x, a.y, a.z, a.w};
            float bv[4] = {b.x, b.y, b.z, b.w};
#pragma unroll
            for (int i = 0; i < 4; i++)
#pragma unroll
                for (int j = 0; j < 4; j++) acc[i][j] = fmaf(av[i], bv[j], acc[i][j]);
        }
        __syncthreads();
    }
#pragma unroll
    for (int i = 0; i < 4; i++) {
        int m = m0 + tm0 + i;
        if (m < count) {
            float4 st = make_float4(acc[i][0], acc[i][1], acc[i][2], acc[i][3]);
            *(float4*)&g_G[(size_t)m * 512 + bn0 + tn0] = st;
        }
    }
}

// ---------------- GRU gates + scatter -----------------------------------------
__global__ void k_gates(const float* __restrict__ memory, const float* __restrict__ last_update,
                        const float* __restrict__ t,
                        const int* __restrict__ src, const int* __restrict__ dst,
                        const float* __restrict__ bih, const float* __restrict__ bhh)
{
    int m = blockIdx.x;
    if (m >= g_count) return;
    int j = g_sel[m];
    int e  = (j < N_EVENTS) ? j : j - N_EVENTS;
    int id = (j < N_EVENTS) ? src[e] : dst[e];
    int d = threadIdx.x;  // 128
    const float* G = &g_G[(size_t)m * 512];
    float g0 = G[d], g1 = G[128 + d], g2 = G[256 + d], g3 = G[384 + d];
    float h = memory[(size_t)id * 128 + d];
    float r = sigmoidf_(g0 + bih[d] + bhh[d]);
    float z = sigmoidf_(g1 + bih[128 + d] + bhh[128 + d]);
    float n = tanhf(g2 + bih[256 + d] + r * (g3 + bhh[256 + d]));
    g_mem_new[(size_t)id * 128 + d] = (1.f - z) * n + z * h;
    if (d == 0) g_lu_new[id] = fmaxf(last_update[id], t[e]);
}

// ---------------- per-edge k,v GEMM: [E x 256] = A[E x 256] @ W^T --------------
// A row = [mem_new[src](128) | timeenc(rel_t)(64) | msg(64)]
// W rows: k: [Wk|We], v: [Wv|We]
__global__ __launch_bounds__(256) void k_kv_gemm(
    const float* __restrict__ t, const float* __restrict__ msg,
    const int* __restrict__ src,
    const float* __restrict__ time_w, const float* __restrict__ time_b,
    const float* __restrict__ Wk, const float* __restrict__ bk,
    const float* __restrict__ Wv, const float* __restrict__ bv,
    const float* __restrict__ We)
{
    const int m0 = blockIdx.x * 64;
    const int bn0 = blockIdx.y * 64;
    const int tid = threadIdx.x;

    __shared__ int   s_src[64], s_ec[64];
    __shared__ float s_rt[64];
    __shared__ float As[16][68];
    __shared__ float Bs[16][68];

    if (tid < 64) {
        int e = min(m0 + tid, N_EVENTS - 1);
        int sn = src[e];
        s_src[tid] = sn; s_ec[tid] = e;
        s_rt[tid] = g_lu_new[sn] - t[e];
    }
    __syncthreads();

    float acc[4][4];
#pragma unroll
    for (int i = 0; i < 4; i++)
#pragma unroll
        for (int j = 0; j < 4; j++) acc[i][j] = 0.f;

    const int tm0 = (tid & 15) * 4;
    const int tn0 = (tid >> 4) * 4;

    for (int k0 = 0; k0 < 256; k0 += 16) {
#pragma unroll
        for (int s = 0; s < 4; s++) {
            int idx = tid + s * 256;
            int kk = idx & 15, m = idx >> 4;
            int k = k0 + kk;
            float v;
            if (k < 128)      v = g_mem_new[(size_t)s_src[m] * 128 + k];
            else if (k < 192) v = cosf(fmaf(s_rt[m], time_w[k - 128], time_b[k - 128]));
            else              v = msg[(size_t)s_ec[m] * 64 + (k - 192)];
            As[kk][m] = v;
        }
#pragma unroll
        for (int s = 0; s < 4; s++) {
            int idx = tid + s * 256;
            int kk = idx & 15, n = idx >> 4;
            int k = k0 + kk;
            int o = bn0 + n;
            float v;
            if (o < 128) v = (k < 128) ? Wk[(size_t)o * 128 + k] : We[(size_t)o * 128 + (k - 128)];
            else { int o2 = o - 128;
                   v = (k < 128) ? Wv[(size_t)o2 * 128 + k] : We[(size_t)o2 * 128 + (k - 128)]; }
            Bs[kk][n] = v;
        }
        __syncthreads();
#pragma unroll
        for (int kk = 0; kk < 16; kk++) {
            float4 a = *(const float4*)&As[kk][tm0];
            float4 b = *(const float4*)&Bs[kk][tn0];
            float av[4] = {a.x, a.y, a.z, a.w};
            float bv[4] = {b.x, b.y, b.z, b.w};
#pragma unroll
            for (int i = 0; i < 4; i++)
#pragma unroll
                for (int j = 0; j < 4; j++) acc[i][j] = fmaf(av[i], bv[j], acc[i][j]);
        }
        __syncthreads();
    }
#pragma unroll
    for (int i = 0; i < 4; i++) {
        int e = m0 + tm0 + i;
        if (e < N_EVENTS) {
#pragma unroll
            for (int j = 0; j < 4; j++) {
                int o = bn0 + tn0 + j;
                float bias = (o < 128) ? bk[o] : bv[o - 128];
                g_kv[(size_t)e * 256 + o] = acc[i][j] + bias;
            }
        }
    }
}

// ---------------- q GEMM + logits + atomic max --------------------------------
__global__ __launch_bounds__(256) void k_q_logit(
    const int* __restrict__ dst,
    const float* __restrict__ Wq, const float* __restrict__ bq)
{
    const int m0 = blockIdx.x * 32;
    const int tid = threadIdx.x;

    __shared__ int   s_dst[32];
    __shared__ float As[16][36];
    __shared__ float Bs[16][132];
    __shared__ float logit_s[64];  // [m][h]

    if (tid < 32) s_dst[tid] = dst[min(m0 + tid, N_EVENTS - 1)];
    if (tid < 64) logit_s[tid] = 0.f;
    __syncthreads();

    float acc[4][4];
#pragma unroll
    for (int i = 0; i < 4; i++)
#pragma unroll
        for (int j = 0; j < 4; j++) acc[i][j] = 0.f;

    const int tm0 = (tid & 7) * 4;
    const int tn0 = (tid >> 3) * 4;

    for (int k0 = 0; k0 < 128; k0 += 16) {
#pragma unroll
        for (int s = 0; s < 2; s++) {
            int idx = tid + s * 256;
            int kk = idx & 15, m = idx >> 4;
            As[kk][m] = g_mem_new[(size_t)s_dst[m] * 128 + k0 + kk];
        }
#pragma unroll
        for (int s = 0; s < 8; s++) {
            int idx = tid + s * 256;
            int kk = idx & 15, n = idx >> 4;
            Bs[kk][n] = Wq[(size_t)n * 128 + k0 + kk];
        }
        __syncthreads();
#pragma unroll
        for (int kk = 0; kk < 16; kk++) {
            float4 a = *(const float4*)&As[kk][tm0];
            float4 b = *(const float4*)&Bs[kk][tn0];
            float av[4] = {a.x, a.y, a.z, a.w};
            float bv[4] = {b.x, b.y, b.z, b.w};
#pragma unroll
            for (int i = 0; i < 4; i++)
#pragma unroll
                for (int j = 0; j < 4; j++) acc[i][j] = fmaf(av[i], bv[j], acc[i][j]);
        }
        __syncthreads();
    }
    const int head = tn0 >> 6;
#pragma unroll
    for (int i = 0; i < 4; i++) {
        int m = m0 + tm0 + i;
        if (m < N_EVENTS) {
            float p = 0.f;
#pragma unroll
            for (int j = 0; j < 4; j++) {
                int o = tn0 + j;
                p = fmaf(acc[i][j] + bq[o], g_kv[(size_t)m * 256 + o], p);
            }
            atomicAdd(&logit_s[(tm0 + i) * 2 + head], p);
        }
    }
    __syncthreads();
    if (tid < 64) {
        int mi = tid >> 1, h = tid & 1;
        int m = m0 + mi;
        if (m < N_EVENTS) {
            float lg = logit_s[tid] * 0.125f;
            g_logit[m * 2 + h] = lg;
            atomicMax(&g_mx[(size_t)s_dst[mi] * 2 + h], enc_f(lg));
        }
    }
}

// ---------------- exp + denom --------------------------------------------------
__global__ void k_expsum(const int* __restrict__ dst) {
    int i = blockIdx.x * blockDim.x + threadIdx.x;
    if (i >= N_EVENTS * 2) return;
    int e = i >> 1, h = i & 1;
    int dn = dst[e];
    float mxv = dec_f(g_mx[dn * 2 + h]);
    float a = expf(g_logit[i] - mxv);
    g_aexp[i] = a;
    atomicAdd(&g_denom[dn * 2 + h], a);
}

// ---------------- skip GEMM over all nodes: z = mem_new @ Wskip^T + bskip -----
__global__ __launch_bounds__(256) void k_skip_gemm(
    const float* __restrict__ Wskip, const float* __restrict__ bskip)
{
    const int m0 = blockIdx.x * 64;
    const int bn0 = blockIdx.y * 64;
    const int tid = threadIdx.x;

    __shared__ float As[16][68];
    __shared__ float Bs[16][68];

    float acc[4][4];
#pragma unroll
    for (int i = 0; i < 4; i++)
#pragma unroll
        for (int j = 0; j < 4; j++) acc[i][j] = 0.f;

    const int tm0 = (tid & 15) * 4;
    const int tn0 = (tid >> 4) * 4;

    for (int k0 = 0; k0 < 128; k0 += 16) {
#pragma unroll
        for (int s = 0; s < 4; s++) {
            int idx = tid + s * 256;
            int kk = idx & 15, m = idx >> 4;
            As[kk][m] = g_mem_new[(size_t)(m0 + m) * 128 + k0 + kk];
        }
#pragma unroll
        for (int s = 0; s < 4; s++) {
            int idx = tid + s * 256;
            int kk = idx & 15, n = idx >> 4;
            Bs[kk][n] = Wskip[(size_t)(bn0 + n) * 128 + k0 + kk];
        }
        __syncthreads();
#pragma unroll
        for (int kk = 0; kk < 16; kk++) {
            float4 a = *(const float4*)&As[kk][tm0];
            float4 b = *(const float4*)&Bs[kk][tn0];
            float av[4] = {a.x, a.y, a.z, a.w};
            float bv[4] = {b.x, b.y, b.z, b.w};
#pragma unroll
            for (int i = 0; i < 4; i++)
#pragma unroll
                for (int j = 0; j < 4; j++) acc[i][j] = fmaf(av[i], bv[j], acc[i][j]);
        }
        __syncthreads();
    }
#pragma unroll
    for (int i = 0; i < 4; i++) {
        int m = m0 + tm0 + i;
#pragma unroll
        for (int j = 0; j < 4; j++) {
            int o = bn0 + tn0 + j;
            g_z[(size_t)m * 128 + o] = acc[i][j] + bskip[o];
        }
    }
}

// ---------------- scatter attention output into z ------------------------------
__global__ void k_scatter(const int* __restrict__ dst) {
    int e = blockIdx.x;
    int d = threadIdx.x;          // 128
    int dn = dst[e];
    int h = d >> 6;
    float attn = g_aexp[e * 2 + h] / g_denom[dn * 2 + h];
    atomicAdd(&g_z[(size_t)dn * 128 + d], attn * g_kv[(size_t)e * 256 + 128 + d]);
}

// ---------------- link predictor -----------------------------------------------
__global__ __launch_bounds__(256) void k_linkpred(
    const int* __restrict__ src, const int* __restrict__ dst,
    const float* __restrict__ Wls, const float* __restrict__ bls,
    const float* __restrict__ Wld, const float* __restrict__ bld,
    const float* __restrict__ Wlf, const float* __restrict__ blf,
    float* __restrict__ out)
{
    const int m0 = blockIdx.x * 32;
    const int tid = threadIdx.x;

    __shared__ int   s_src[32], s_dst[32];
    __shared__ float As[16][36];
    __shared__ float Bs[16][132];
    __shared__ float out_s[32];

    if (tid < 32) {
        int e = min(m0 + tid, N_EVENTS - 1);
        s_src[tid] = src[e];
        s_dst[tid] = dst[e];
        out_s[tid] = 0.f;
    }
    __syncthreads();

    float acc[4][4];
#pragma unroll
    for (int i = 0; i < 4; i++)
#pragma unroll
        for (int j = 0; j < 4; j++) acc[i][j] = 0.f;

    const int tm0 = (tid & 7) * 4;
    const int tn0 = (tid >> 3) * 4;

    for (int k0 = 0; k0 < 256; k0 += 16) {
#pragma unroll
        for (int s = 0; s < 2; s++) {
            int idx = tid + s * 256;
            int kk = idx & 15, m = idx >> 4;
            int k = k0 + kk;
            float v = (k < 128) ? g_z[(size_t)s_src[m] * 128 + k]
                                : g_z[(size_t)s_dst[m] * 128 + (k - 128)];
            As[kk][m] = v;
        }
#pragma unroll
        for (int s = 0; s < 8; s++) {
            int idx = tid + s * 256;
            int kk = idx & 15, n = idx >> 4;
            int k = k0 + kk;
            float v = (k < 128) ? Wls[(size_t)n * 128 + k] : Wld[(size_t)n * 128 + (k - 128)];
            Bs[kk][n] = v;
        }
        __syncthreads();
#pragma unroll
        for (int kk = 0; kk < 16; kk++) {
            float4 a = *(const float4*)&As[kk][tm0];
            float4 b = *(const float4*)&Bs[kk][tn0];
            float av[4] = {a.x, a.y, a.z, a.w};
            float bv[4] = {b.x, b.y, b.z, b.w};
#pragma unroll
            for (int i = 0; i < 4; i++)
#pragma unroll
                for (int j = 0; j < 4; j++) acc[i][j] = fmaf(av[i], bv[j], acc[i][j]);
        }
        __syncthreads();
    }
#pragma unroll
    for (int i = 0; i < 4; i++) {
        int m = m0 + tm0 + i;
        if (m < N_EVENTS) {
            float p = 0.f;
#pragma unroll
            for (int j = 0; j < 4; j++) {
                int o = tn0 + j;
                float v = acc[i][j] + bls[o] + bld[o];
                v = fmaxf(v, 0.f);
                p = fmaf(v, Wlf[o], p);
            }
            atomicAdd(&out_s[tm0 + i], p);
        }
    }
    __syncthreads();
    if (tid < 32 && m0 + tid < N_EVENTS) {
        out[m0 + tid] = out_s[tid] + blf[0];
    }
}

// ---------------- launch --------------------------------------------------------
extern "C" void kernel_launch(void* const* d_in, const int* in_sizes, int n_in,
                              void* d_out, int out_size)
{
    const float* memory      = (const float*)d_in[0];
    const float* last_update = (const float*)d_in[1];
    const float* t           = (const float*)d_in[2];
    const float* msg         = (const float*)d_in[3];
    const int*   src         = (const int*)d_in[4];
    const int*   dst         = (const int*)d_in[5];
    const float* time_w      = (const float*)d_in[6];
    const float* time_b      = (const float*)d_in[7];
    const float* gru_Wih     = (const float*)d_in[8];
    const float* gru_bih     = (const float*)d_in[9];
    const float* gru_Whh     = (const float*)d_in[10];
    const float* gru_bhh     = (const float*)d_in[11];
    const float* Wq          = (const float*)d_in[12];
    const float* bq          = (const float*)d_in[13];
    const float* Wk          = (const float*)d_in[14];
    const float* bk          = (const float*)d_in[15];
    const float* Wv          = (const float*)d_in[16];
    const float* bv          = (const float*)d_in[17];
    const float* We          = (const float*)d_in[18];
    const float* Wskip       = (const float*)d_in[19];
    const float* bskip       = (const float*)d_in[20];
    const float* Wls         = (const float*)d_in[21];
    const float* bls         = (const float*)d_in[22];
    const float* Wld         = (const float*)d_in[23];
    const float* bld         = (const float*)d_in[24];
    const float* Wlf         = (const float*)d_in[25];
    const float* blf         = (const float*)d_in[26];
    float* out = (float*)d_out;

    // 1. init scratch
    k_init<<<(2 * N_NODES + 255) / 256, 256>>>();
    // 2. copy memory / last_update into mutable buffers
    k_copy<<<(N_NODES * (MEMD / 4) + 255) / 256, 256>>>((const float4*)memory, last_update);
    // 3. last aggregator
    k_lastpos<<<(TWO_E + 255) / 256, 256>>>(src, dst);
    k_compact<<<(TWO_E + 255) / 256, 256>>>(src, dst);
    // 4. GRU (compact rows only)
    {
        dim3 grid((TWO_E + 63) / 64, 8);
        k_gru_gemm<<<grid, 256>>>(memory, last_update, t, msg, src, dst,
                                  time_w, time_b, gru_Wih, gru_Whh);
    }
    k_gates<<<TWO_E, 128>>>(memory, last_update, t, src, dst, gru_bih, gru_bhh);
    // 5. per-edge k/v
    {
        dim3 grid((N_EVENTS + 63) / 64, 4);
        k_kv_gemm<<<grid, 256>>>(t, msg, src, time_w, time_b, Wk, bk, Wv, bv, We);
    }
    // 6. q + logits + segment max
    k_q_logit<<<(N_EVENTS + 31) / 32, 256>>>(dst, Wq, bq);
    // 7. exp + denom
    k_expsum<<<(N_EVENTS * 2 + 255) / 256, 256>>>(dst);
    // 8. skip connection (all nodes)
    {
        dim3 grid(N_NODES / 64, 2);
        k_skip_gemm<<<grid, 256>>>(Wskip, bskip);
    }
    // 9. scatter attention output
    k_scatter<<<N_EVENTS, 128>>>(dst);
    // 10. link predictor
    k_linkpred<<<(N_EVENTS + 31) / 32, 256>>>(src, dst, Wls, bls, Wld, bld, Wlf, blf, out);
}

// round 4
// speedup vs baseline: 1.4101x; 1.4101x over previous
#include <cuda_runtime.h>
#include <math.h>
#include <stdint.h>

#define N_NODES 200000
#define N_EVENTS 50000
#define MEMD 128
#define TWO_E (2 * N_EVENTS)

// ---------------- scratch (static device globals; no runtime allocation) ----
__device__ int      g_last_pos[N_NODES];
__device__ int      g_sel[TWO_E];
__device__ int      g_count;
__device__ float    g_mem_new[(size_t)N_NODES * MEMD];
__device__ float    g_lu_new[N_NODES];
__device__ float    g_G[(size_t)TWO_E * 512];          // GRU pre-gate outputs
__device__ float    g_kv[(size_t)N_EVENTS * 256];      // per-edge k (0:128) and v (128:256)
__device__ float    g_logit[N_EVENTS * 2];
__device__ float    g_aexp[N_EVENTS * 2];
__device__ unsigned g_mx[N_NODES * 2];                 // order-preserving encoded max logit
__device__ float    g_denom[N_NODES * 2];
__device__ float    g_z[(size_t)N_NODES * MEMD];       // skip + attention out

// order-preserving float<->uint encoding for atomicMax on floats
__device__ __forceinline__ unsigned enc_f(float x) {
    unsigned u = __float_as_uint(x);
    return (u & 0x80000000u) ? ~u : (u | 0x80000000u);
}
__device__ __forceinline__ float dec_f(unsigned u) {
    unsigned v = (u & 0x80000000u) ? (u & 0x7FFFFFFFu) : ~u;
    return __uint_as_float(v);
}
__device__ __forceinline__ float sigmoidf_(float x) { return 1.f / (1.f + expf(-x)); }

// tf32 helpers
__device__ __forceinline__ uint32_t f2tf32(float x) {
    uint32_t y;
    asm("cvt.rna.tf32.f32 %0, %1;" : "=r"(y) : "f"(x));
    return y;
}
__device__ __forceinline__ void mma_tf32(float4& d, const uint32_t a[4], const uint32_t b[2]) {
    asm volatile(
        "mma.sync.aligned.m16n8k8.row.col.f32.tf32.tf32.f32 "
        "{%0,%1,%2,%3}, {%4,%5,%6,%7}, {%8,%9}, {%0,%1,%2,%3};\n"
        : "+f"(d.x), "+f"(d.y), "+f"(d.z), "+f"(d.w)
        : "r"(a[0]), "r"(a[1]), "r"(a[2]), "r"(a[3]), "r"(b[0]), "r"(b[1]));
}

// ---------------- init / copy / last-pos / compact ---------------------------
__global__ void k_init() {
    int i = blockIdx.x * blockDim.x + threadIdx.x;
    if (i < N_NODES) g_last_pos[i] = -1;
    if (i < 2 * N_NODES) { g_mx[i] = 0u; g_denom[i] = 0.f; }
    if (i == 0) g_count = 0;
}

__global__ void k_copy(const float4* __restrict__ mem, const float* __restrict__ lu) {
    int i = blockIdx.x * blockDim.x + threadIdx.x;
    if (i < N_NODES * (MEMD / 4)) ((float4*)g_mem_new)[i] = mem[i];
    if (i < N_NODES) g_lu_new[i] = lu[i];
}

__global__ void k_lastpos(const int* __restrict__ src, const int* __restrict__ dst) {
    int j = blockIdx.x * blockDim.x + threadIdx.x;
    if (j >= TWO_E) return;
    int id = (j < N_EVENTS) ? src[j] : dst[j - N_EVENTS];
    atomicMax(&g_last_pos[id], j);
}

__global__ void k_compact(const int* __restrict__ src, const int* __restrict__ dst) {
    int j = blockIdx.x * blockDim.x + threadIdx.x;
    if (j >= TWO_E) return;
    int id = (j < N_EVENTS) ? src[j] : dst[j - N_EVENTS];
    if (g_last_pos[id] == j) {
        int p = atomicAdd(&g_count, 1);
        g_sel[p] = j;
    }
}

// ================= TF32 MMA GEMM kernels =====================================
// Common tile: BM=128, BN=64, BK=16, 256 threads (8 warps, 4x2 warp grid),
// warp tile 32x32 = 2 m-subtiles x 4 n-subtiles of m16n8k8.

// ---------------- GRU GEMM: G[m][0:512] ---------------------------------------
// x' = [mem[id](128) | mem[other](128) | msg(64) | timeenc(64) | mem[id](128)]
// col groups: [0,256) r,z : K=[0,512); [256,384) i_n : K=[0,384); [384,512) h_n : K=[384,512)
__global__ __launch_bounds__(256) void k_gru_gemm(
    const float* __restrict__ memory, const float* __restrict__ last_update,
    const float* __restrict__ t, const float* __restrict__ msg,
    const int* __restrict__ src, const int* __restrict__ dst,
    const float* __restrict__ time_w, const float* __restrict__ time_b,
    const float* __restrict__ Wih, const float* __restrict__ Whh)
{
    const int count = g_count;
    const int m0 = blockIdx.x * 128;
    if (m0 >= count) return;
    const int bn0 = blockIdx.y * 64;
    const int grp = bn0 >> 7;                     // 0,1 = r,z ; 2 = i_n ; 3 = h_n
    const int k_lo = (grp == 3) ? 384 : 0;
    const int k_hi = (grp == 2) ? 384 : 512;
    const int tid = threadIdx.x;
    const int lane = tid & 31;
    const int warp = tid >> 5;
    const int warp_m = warp & 3;                  // 0..3
    const int warp_n = warp >> 2;                 // 0..1
    const int g_ = lane >> 2, t_ = lane & 3;

    __shared__ int      s_id[128], s_oth[128], s_e[128];
    __shared__ float    s_dt[128];
    __shared__ uint32_t As[16][136];
    __shared__ uint32_t Bs[16][72];

    if (tid < 128) {
        int mm = min(m0 + tid, count - 1);
        int j = g_sel[mm];
        int e  = (j < N_EVENTS) ? j : j - N_EVENTS;
        int id = (j < N_EVENTS) ? src[e] : dst[e];
        int ot = (j < N_EVENTS) ? dst[e] : src[e];
        s_id[tid] = id; s_oth[tid] = ot; s_e[tid] = e;
        s_dt[tid] = t[e] - last_update[id];
    }
    __syncthreads();

    float4 acc[2][4];
#pragma unroll
    for (int i = 0; i < 2; i++)
#pragma unroll
        for (int j = 0; j < 4; j++) acc[i][j] = make_float4(0.f, 0.f, 0.f, 0.f);

    for (int k0 = k_lo; k0 < k_hi; k0 += 16) {
        // stage A (gathered): 128 rows x 16 k = 2048 elems, 8/thread
#pragma unroll
        for (int s = 0; s < 8; s++) {
            int idx = tid + s * 256;
            int kk = idx & 15, m = idx >> 4;
            int k = k0 + kk;
            float v;
            if (k < 128)       v = memory[(size_t)s_id[m] * 128 + k];
            else if (k < 256)  v = memory[(size_t)s_oth[m] * 128 + (k - 128)];
            else if (k < 320)  v = msg[(size_t)s_e[m] * 64 + (k - 256)];
            else if (k < 384)  v = cosf(fmaf(s_dt[m], time_w[k - 320], time_b[k - 320]));
            else               v = memory[(size_t)s_id[m] * 128 + (k - 384)];
            As[kk][m] = f2tf32(v);
        }
        // stage B: 64 cols x 16 k = 1024 elems, 4/thread
#pragma unroll
        for (int s = 0; s < 4; s++) {
            int idx = tid + s * 256;
            int kk = idx & 15, n = idx >> 4;
            int k = k0 + kk;
            int r = (bn0 + n) & 127;
            float v;
            if (grp < 2)       v = (k < 384) ? Wih[(size_t)(grp * 128 + r) * 384 + k]
                                             : Whh[(size_t)(grp * 128 + r) * 128 + (k - 384)];
            else if (grp == 2) v = Wih[(size_t)(256 + r) * 384 + k];
            else               v = Whh[(size_t)(256 + r) * 128 + (k - 384)];
            Bs[kk][n] = f2tf32(v);
        }
        __syncthreads();
#pragma unroll
        for (int ks = 0; ks < 2; ks++) {
            const int kb = ks * 8;
            uint32_t a[2][4], b[4][2];
#pragma unroll
            for (int mt = 0; mt < 2; mt++) {
                int rb = warp_m * 32 + mt * 16 + g_;
                a[mt][0] = As[kb + t_][rb];
                a[mt][1] = As[kb + t_][rb + 8];
                a[mt][2] = As[kb + t_ + 4][rb];
                a[mt][3] = As[kb + t_ + 4][rb + 8];
            }
#pragma unroll
            for (int nt = 0; nt < 4; nt++) {
                int cb = warp_n * 32 + nt * 8 + g_;
                b[nt][0] = Bs[kb + t_][cb];
                b[nt][1] = Bs[kb + t_ + 4][cb];
            }
#pragma unroll
            for (int mt = 0; mt < 2; mt++)
#pragma unroll
                for (int nt = 0; nt < 4; nt++) mma_tf32(acc[mt][nt], a[mt], b[nt]);
        }
        __syncthreads();
    }
#pragma unroll
    for (int mt = 0; mt < 2; mt++)
#pragma unroll
        for (int nt = 0; nt < 4; nt++) {
            int r0 = m0 + warp_m * 32 + mt * 16 + g_;
            int c  = bn0 + warp_n * 32 + nt * 8 + 2 * t_;
            if (r0 < count)
                *(float2*)&g_G[(size_t)r0 * 512 + c] = make_float2(acc[mt][nt].x, acc[mt][nt].y);
            if (r0 + 8 < count)
                *(float2*)&g_G[(size_t)(r0 + 8) * 512 + c] = make_float2(acc[mt][nt].z, acc[mt][nt].w);
        }
}

// ---------------- GRU gates + scatter -----------------------------------------
__global__ void k_gates(const float* __restrict__ memory, const float* __restrict__ last_update,
                        const float* __restrict__ t,
                        const int* __restrict__ src, const int* __restrict__ dst,
                        const float* __restrict__ bih, const float* __restrict__ bhh)
{
    int m = blockIdx.x;
    if (m >= g_count) return;
    int j = g_sel[m];
    int e  = (j < N_EVENTS) ? j : j - N_EVENTS;
    int id = (j < N_EVENTS) ? src[e] : dst[e];
    int d = threadIdx.x;  // 128
    const float* G = &g_G[(size_t)m * 512];
    float g0 = G[d], g1 = G[128 + d], g2 = G[256 + d], g3 = G[384 + d];
    float h = memory[(size_t)id * 128 + d];
    float r = sigmoidf_(g0 + bih[d] + bhh[d]);
    float z = sigmoidf_(g1 + bih[128 + d] + bhh[128 + d]);
    float n = tanhf(g2 + bih[256 + d] + r * (g3 + bhh[256 + d]));
    g_mem_new[(size_t)id * 128 + d] = (1.f - z) * n + z * h;
    if (d == 0) g_lu_new[id] = fmaxf(last_update[id], t[e]);
}

// ---------------- per-edge k,v GEMM: [E x 256] --------------------------------
// A row = [mem_new[src](128) | timeenc(rel_t)(64) | msg(64)], K=256
// W rows: k: [Wk|We], v: [Wv|We]
__global__ __launch_bounds__(256) void k_kv_gemm(
    const float* __restrict__ t, const float* __restrict__ msg,
    const int* __restrict__ src,
    const float* __restrict__ time_w, const float* __restrict__ time_b,
    const float* __restrict__ Wk, const float* __restrict__ bk,
    const float* __restrict__ Wv, const float* __restrict__ bv,
    const float* __restrict__ We)
{
    const int m0 = blockIdx.x * 128;
    const int bn0 = blockIdx.y * 64;
    const int tid = threadIdx.x;
    const int lane = tid & 31;
    const int warp = tid >> 5;
    const int warp_m = warp & 3;
    const int warp_n = warp >> 2;
    const int g_ = lane >> 2, t_ = lane & 3;

    __shared__ int      s_src[128], s_ec[128];
    __shared__ float    s_rt[128];
    __shared__ uint32_t As[16][136];
    __shared__ uint32_t Bs[16][72];

    if (tid < 128) {
        int e = min(m0 + tid, N_EVENTS - 1);
        int sn = src[e];
        s_src[tid] = sn; s_ec[tid] = e;
        s_rt[tid] = g_lu_new[sn] - t[e];
    }
    __syncthreads();

    float4 acc[2][4];
#pragma unroll
    for (int i = 0; i < 2; i++)
#pragma unroll
        for (int j = 0; j < 4; j++) acc[i][j] = make_float4(0.f, 0.f, 0.f, 0.f);

    for (int k0 = 0; k0 < 256; k0 += 16) {
#pragma unroll
        for (int s = 0; s < 8; s++) {
            int idx = tid + s * 256;
            int kk = idx & 15, m = idx >> 4;
            int k = k0 + kk;
            float v;
            if (k < 128)      v = g_mem_new[(size_t)s_src[m] * 128 + k];
            else if (k < 192) v = cosf(fmaf(s_rt[m], time_w[k - 128], time_b[k - 128]));
            else              v = msg[(size_t)s_ec[m] * 64 + (k - 192)];
            As[kk][m] = f2tf32(v);
        }
#pragma unroll
        for (int s = 0; s < 4; s++) {
            int idx = tid + s * 256;
            int kk = idx & 15, n = idx >> 4;
            int k = k0 + kk;
            int o = bn0 + n;
            float v;
            if (o < 128) v = (k < 128) ? Wk[(size_t)o * 128 + k] : We[(size_t)o * 128 + (k - 128)];
            else { int o2 = o - 128;
                   v = (k < 128) ? Wv[(size_t)o2 * 128 + k] : We[(size_t)o2 * 128 + (k - 128)]; }
            Bs[kk][n] = f2tf32(v);
        }
        __syncthreads();
#pragma unroll
        for (int ks = 0; ks < 2; ks++) {
            const int kb = ks * 8;
            uint32_t a[2][4], b[4][2];
#pragma unroll
            for (int mt = 0; mt < 2; mt++) {
                int rb = warp_m * 32 + mt * 16 + g_;
                a[mt][0] = As[kb + t_][rb];
                a[mt][1] = As[kb + t_][rb + 8];
                a[mt][2] = As[kb + t_ + 4][rb];
                a[mt][3] = As[kb + t_ + 4][rb + 8];
            }
#pragma unroll
            for (int nt = 0; nt < 4; nt++) {
                int cb = warp_n * 32 + nt * 8 + g_;
                b[nt][0] = Bs[kb + t_][cb];
                b[nt][1] = Bs[kb + t_ + 4][cb];
            }
#pragma unroll
            for (int mt = 0; mt < 2; mt++)
#pragma unroll
                for (int nt = 0; nt < 4; nt++) mma_tf32(acc[mt][nt], a[mt], b[nt]);
        }
        __syncthreads();
    }
#pragma unroll
    for (int mt = 0; mt < 2; mt++)
#pragma unroll
        for (int nt = 0; nt < 4; nt++) {
            int r0 = m0 + warp_m * 32 + mt * 16 + g_;
            int c  = bn0 + warp_n * 32 + nt * 8 + 2 * t_;
            float b0 = (c < 128) ? bk[c] : bv[c - 128];
            float b1 = (c + 1 < 128) ? bk[c + 1] : bv[c + 1 - 128];
            if (r0 < N_EVENTS)
                *(float2*)&g_kv[(size_t)r0 * 256 + c] =
                    make_float2(acc[mt][nt].x + b0, acc[mt][nt].y + b1);
            if (r0 + 8 < N_EVENTS)
                *(float2*)&g_kv[(size_t)(r0 + 8) * 256 + c] =
                    make_float2(acc[mt][nt].z + b0, acc[mt][nt].w + b1);
        }
}

// ---------------- q GEMM + logits + atomic max --------------------------------
__global__ __launch_bounds__(256) void k_q_logit(
    const int* __restrict__ dst,
    const float* __restrict__ Wq, const float* __restrict__ bq)
{
    const int m0 = blockIdx.x * 32;
    const int tid = threadIdx.x;

    __shared__ int   s_dst[32];
    __shared__ float As[16][36];
    __shared__ float Bs[16][132];
    __shared__ float logit_s[64];  // [m][h]

    if (tid < 32) s_dst[tid] = dst[min(m0 + tid, N_EVENTS - 1)];
    if (tid < 64) logit_s[tid] = 0.f;
    __syncthreads();

    float acc[4][4];
#pragma unroll
    for (int i = 0; i < 4; i++)
#pragma unroll
        for (int j = 0; j < 4; j++) acc[i][j] = 0.f;

    const int tm0 = (tid & 7) * 4;
    const int tn0 = (tid >> 3) * 4;

    for (int k0 = 0; k0 < 128; k0 += 16) {
#pragma unroll
        for (int s = 0; s < 2; s++) {
            int idx = tid + s * 256;
            int kk = idx & 15, m = idx >> 4;
            As[kk][m] = g_mem_new[(size_t)s_dst[m] * 128 + k0 + kk];
        }
#pragma unroll
        for (int s = 0; s < 8; s++) {
            int idx = tid + s * 256;
            int kk = idx & 15, n = idx >> 4;
            Bs[kk][n] = Wq[(size_t)n * 128 + k0 + kk];
        }
        __syncthreads();
#pragma unroll
        for (int kk = 0; kk < 16; kk++) {
            float4 a = *(const float4*)&As[kk][tm0];
            float4 b = *(const float4*)&Bs[kk][tn0];
            float av[4] = {a.x, a.y, a.z, a.w};
            float bv[4] = {b.x, b.y, b.z, b.w};
#pragma unroll
            for (int i = 0; i < 4; i++)
#pragma unroll
                for (int j = 0; j < 4; j++) acc[i][j] = fmaf(av[i], bv[j], acc[i][j]);
        }
        __syncthreads();
    }
    const int head = tn0 >> 6;
#pragma unroll
    for (int i = 0; i < 4; i++) {
        int m = m0 + tm0 + i;
        if (m < N_EVENTS) {
            float p = 0.f;
#pragma unroll
            for (int j = 0; j < 4; j++) {
                int o = tn0 + j;
                p = fmaf(acc[i][j] + bq[o], g_kv[(size_t)m * 256 + o], p);
            }
            atomicAdd(&logit_s[(tm0 + i) * 2 + head], p);
        }
    }
    __syncthreads();
    if (tid < 64) {
        int mi = tid >> 1, h = tid & 1;
        int m = m0 + mi;
        if (m < N_EVENTS) {
            float lg = logit_s[tid] * 0.125f;
            g_logit[m * 2 + h] = lg;
            atomicMax(&g_mx[(size_t)s_dst[mi] * 2 + h], enc_f(lg));
        }
    }
}

// ---------------- exp + denom --------------------------------------------------
__global__ void k_expsum(const int* __restrict__ dst) {
    int i = blockIdx.x * blockDim.x + threadIdx.x;
    if (i >= N_EVENTS * 2) return;
    int e = i >> 1, h = i & 1;
    int dn = dst[e];
    float mxv = dec_f(g_mx[dn * 2 + h]);
    float a = expf(g_logit[i] - mxv);
    g_aexp[i] = a;
    atomicAdd(&g_denom[dn * 2 + h], a);
}

// ---------------- skip GEMM over all nodes: z = mem_new @ Wskip^T + bskip -----
__global__ __launch_bounds__(256) void k_skip_gemm(
    const float* __restrict__ Wskip, const float* __restrict__ bskip)
{
    const int m0 = blockIdx.x * 128;
    const int bn0 = blockIdx.y * 64;
    const int tid = threadIdx.x;
    const int lane = tid & 31;
    const int warp = tid >> 5;
    const int warp_m = warp & 3;
    const int warp_n = warp >> 2;
    const int g_ = lane >> 2, t_ = lane & 3;

    __shared__ uint32_t As[16][136];
    __shared__ uint32_t Bs[16][72];

    float4 acc[2][4];
#pragma unroll
    for (int i = 0; i < 2; i++)
#pragma unroll
        for (int j = 0; j < 4; j++) acc[i][j] = make_float4(0.f, 0.f, 0.f, 0.f);

    for (int k0 = 0; k0 < 128; k0 += 16) {
#pragma unroll
        for (int s = 0; s < 8; s++) {
            int idx = tid + s * 256;
            int kk = idx & 15, m = idx >> 4;
            int mg = min(m0 + m, N_NODES - 1);
            As[kk][m] = f2tf32(g_mem_new[(size_t)mg * 128 + k0 + kk]);
        }
#pragma unroll
        for (int s = 0; s < 4; s++) {
            int idx = tid + s * 256;
            int kk = idx & 15, n = idx >> 4;
            Bs[kk][n] = f2tf32(Wskip[(size_t)(bn0 + n) * 128 + k0 + kk]);
        }
        __syncthreads();
#pragma unroll
        for (int ks = 0; ks < 2; ks++) {
            const int kb = ks * 8;
            uint32_t a[2][4], b[4][2];
#pragma unroll
            for (int mt = 0; mt < 2; mt++) {
                int rb = warp_m * 32 + mt * 16 + g_;
                a[mt][0] = As[kb + t_][rb];
                a[mt][1] = As[kb + t_][rb + 8];
                a[mt][2] = As[kb + t_ + 4][rb];
                a[mt][3] = As[kb + t_ + 4][rb + 8];
            }
#pragma unroll
            for (int nt = 0; nt < 4; nt++) {
                int cb = warp_n * 32 + nt * 8 + g_;
                b[nt][0] = Bs[kb + t_][cb];
                b[nt][1] = Bs[kb + t_ + 4][cb];
            }
#pragma unroll
            for (int mt = 0; mt < 2; mt++)
#pragma unroll
                for (int nt = 0; nt < 4; nt++) mma_tf32(acc[mt][nt], a[mt], b[nt]);
        }
        __syncthreads();
    }
#pragma unroll
    for (int mt = 0; mt < 2; mt++)
#pragma unroll
        for (int nt = 0; nt < 4; nt++) {
            int r0 = m0 + warp_m * 32 + mt * 16 + g_;
            int c  = bn0 + warp_n * 32 + nt * 8 + 2 * t_;
            float b0 = bskip[c], b1 = bskip[c + 1];
            if (r0 < N_NODES)
                *(float2*)&g_z[(size_t)r0 * 128 + c] =
                    make_float2(acc[mt][nt].x + b0, acc[mt][nt].y + b1);
            if (r0 + 8 < N_NODES)
                *(float2*)&g_z[(size_t)(r0 + 8) * 128 + c] =
                    make_float2(acc[mt][nt].z + b0, acc[mt][nt].w + b1);
        }
}

// ---------------- scatter attention output into z ------------------------------
__global__ void k_scatter(const int* __restrict__ dst) {
    int e = blockIdx.x;
    int d = threadIdx.x;          // 128
    int dn = dst[e];
    int h = d >> 6;
    float attn = g_aexp[e * 2 + h] / g_denom[dn * 2 + h];
    atomicAdd(&g_z[(size_t)dn * 128 + d], attn * g_kv[(size_t)e * 256 + 128 + d]);
}

// ---------------- link predictor -----------------------------------------------
__global__ __launch_bounds__(256) void k_linkpred(
    const int* __restrict__ src, const int* __restrict__ dst,
    const float* __restrict__ Wls, const float* __restrict__ bls,
    const float* __restrict__ Wld, const float* __restrict__ bld,
    const float* __restrict__ Wlf, const float* __restrict__ blf,
    float* __restrict__ out)
{
    const int m0 = blockIdx.x * 32;
    const int tid = threadIdx.x;

    __shared__ int   s_src[32], s_dst[32];
    __shared__ float As[16][36];
    __shared__ float Bs[16][132];
    __shared__ float out_s[32];

    if (tid < 32) {
        int e = min(m0 + tid, N_EVENTS - 1);
        s_src[tid] = src[e];
        s_dst[tid] = dst[e];
        out_s[tid] = 0.f;
    }
    __syncthreads();

    float acc[4][4];
#pragma unroll
    for (int i = 0; i < 4; i++)
#pragma unroll
        for (int j = 0; j < 4; j++) acc[i][j] = 0.f;

    const int tm0 = (tid & 7) * 4;
    const int tn0 = (tid >> 3) * 4;

    for (int k0 = 0; k0 < 256; k0 += 16) {
#pragma unroll
        for (int s = 0; s < 2; s++) {
            int idx = tid + s * 256;
            int kk = idx & 15, m = idx >> 4;
            int k = k0 + kk;
            float v = (k < 128) ? g_z[(size_t)s_src[m] * 128 + k]
                                : g_z[(size_t)s_dst[m] * 128 + (k - 128)];
            As[kk][m] = v;
        }
#pragma unroll
        for (int s = 0; s < 8; s++) {
            int idx = tid + s * 256;
            int kk = idx & 15, n = idx >> 4;
            int k = k0 + kk;
            float v = (k < 128) ? Wls[(size_t)n * 128 + k] : Wld[(size_t)n * 128 + (k - 128)];
            Bs[kk][n] = v;
        }
        __syncthreads();
#pragma unroll
        for (int kk = 0; kk < 16; kk++) {
            float4 a = *(const float4*)&As[kk][tm0];
            float4 b = *(const float4*)&Bs[kk][tn0];
            float av[4] = {a.x, a.y, a.z, a.w};
            float bv[4] = {b.x, b.y, b.z, b.w};
#pragma unroll
            for (int i = 0; i < 4; i++)
#pragma unroll
                for (int j = 0; j < 4; j++) acc[i][j] = fmaf(av[i], bv[j], acc[i][j]);
        }
        __syncthreads();
    }
#pragma unroll
    for (int i = 0; i < 4; i++) {
        int m = m0 + tm0 + i;
        if (m < N_EVENTS) {
            float p = 0.f;
#pragma unroll
            for (int j = 0; j < 4; j++) {
                int o = tn0 + j;
                float v = acc[i][j] + bls[o] + bld[o];
                v = fmaxf(v, 0.f);
                p = fmaf(v, Wlf[o], p);
            }
            atomicAdd(&out_s[tm0 + i], p);
        }
    }
    __syncthreads();
    if (tid < 32 && m0 + tid < N_EVENTS) {
        out[m0 + tid] = out_s[tid] + blf[0];
    }
}

// ---------------- launch --------------------------------------------------------
extern "C" void kernel_launch(void* const* d_in, const int* in_sizes, int n_in,
                              void* d_out, int out_size)
{
    const float* memory      = (const float*)d_in[0];
    const float* last_update = (const float*)d_in[1];
    const float* t           = (const float*)d_in[2];
    const float* msg         = (const float*)d_in[3];
    const int*   src         = (const int*)d_in[4];
    const int*   dst         = (const int*)d_in[5];
    const float* time_w      = (const float*)d_in[6];
    const float* time_b      = (const float*)d_in[7];
    const float* gru_Wih     = (const float*)d_in[8];
    const float* gru_bih     = (const float*)d_in[9];
    const float* gru_Whh     = (const float*)d_in[10];
    const float* gru_bhh     = (const float*)d_in[11];
    const float* Wq          = (const float*)d_in[12];
    const float* bq          = (const float*)d_in[13];
    const float* Wk          = (const float*)d_in[14];
    const float* bk          = (const float*)d_in[15];
    const float* Wv          = (const float*)d_in[16];
    const float* bv          = (const float*)d_in[17];
    const float* We          = (const float*)d_in[18];
    const float* Wskip       = (const float*)d_in[19];
    const float* bskip       = (const float*)d_in[20];
    const float* Wls         = (const float*)d_in[21];
    const float* bls         = (const float*)d_in[22];
    const float* Wld         = (const float*)d_in[23];
    const float* bld         = (const float*)d_in[24];
    const float* Wlf         = (const float*)d_in[25];
    const float* blf         = (const float*)d_in[26];
    float* out = (float*)d_out;

    // 1. init scratch
    k_init<<<(2 * N_NODES + 255) / 256, 256>>>();
    // 2. copy memory / last_update into mutable buffers
    k_copy<<<(N_NODES * (MEMD / 4) + 255) / 256, 256>>>((const float4*)memory, last_update);
    // 3. last aggregator
    k_lastpos<<<(TWO_E + 255) / 256, 256>>>(src, dst);
    k_compact<<<(TWO_E + 255) / 256, 256>>>(src, dst);
    // 4. GRU (compact rows only) — tf32 MMA
    {
        dim3 grid((TWO_E + 127) / 128, 8);
        k_gru_gemm<<<grid, 256>>>(memory, last_update, t, msg, src, dst,
                                  time_w, time_b, gru_Wih, gru_Whh);
    }
    k_gates<<<TWO_E, 128>>>(memory, last_update, t, src, dst, gru_bih, gru_bhh);
    // 5. per-edge k/v — tf32 MMA
    {
        dim3 grid((N_EVENTS + 127) / 128, 4);
        k_kv_gemm<<<grid, 256>>>(t, msg, src, time_w, time_b, Wk, bk, Wv, bv, We);
    }
    // 6. q + logits + segment max
    k_q_logit<<<(N_EVENTS + 31) / 32, 256>>>(dst, Wq, bq);
    // 7. exp + denom
    k_expsum<<<(N_EVENTS * 2 + 255) / 256, 256>>>(dst);
    // 8. skip connection (all nodes) — tf32 MMA
    {
        dim3 grid((N_NODES + 127) / 128, 2);
        k_skip_gemm<<<grid, 256>>>(Wskip, bskip);
    }
    // 9. scatter attention output
    k_scatter<<<N_EVENTS, 128>>>(dst);
    // 10. link predictor
    k_linkpred<<<(N_EVENTS + 31) / 32, 256>>>(src, dst, Wls, bls, Wld, bld, Wlf, blf, out);
}

// round 5
// speedup vs baseline: 1.5994x; 1.1342x over previous
#include <cuda_runtime.h>
#include <math.h>
#include <stdint.h>

#define N_NODES 200000
#define N_EVENTS 50000
#define MEMD 128
#define TWO_E (2 * N_EVENTS)

// ---------------- scratch (static device globals) ----------------------------
__device__ int      g_last_pos[N_NODES];
__device__ int      g_sel[TWO_E];
__device__ int      g_count;
__device__ float    g_mem_new[(size_t)N_NODES * MEMD];
__device__ float    g_lu_new[N_NODES];
__device__ float    g_G[(size_t)TWO_E * 512];
__device__ float    g_kv[(size_t)N_EVENTS * 256];
__device__ float    g_logit[N_EVENTS * 2];
__device__ float    g_aexp[N_EVENTS * 2];
__device__ unsigned g_mx[N_NODES * 2];
__device__ float    g_denom[N_NODES * 2];
__device__ float    g_z[(size_t)N_NODES * MEMD];
__device__ float    g_te[(size_t)TWO_E * 64];     // GRU time-enc per selected row
__device__ float    g_te2[(size_t)N_EVENTS * 64]; // edge time-enc

__device__ __forceinline__ unsigned enc_f(float x) {
    unsigned u = __float_as_uint(x);
    return (u & 0x80000000u) ? ~u : (u | 0x80000000u);
}
__device__ __forceinline__ float dec_f(unsigned u) {
    unsigned v = (u & 0x80000000u) ? (u & 0x7FFFFFFFu) : ~u;
    return __uint_as_float(v);
}
__device__ __forceinline__ float sigmoidf_(float x) { return 1.f / (1.f + expf(-x)); }

__device__ __forceinline__ uint32_t f2tf32(float x) {
    uint32_t y;
    asm("cvt.rna.tf32.f32 %0, %1;" : "=r"(y) : "f"(x));
    return y;
}
__device__ __forceinline__ void mma_tf32(float4& d, const uint32_t a[4], const uint32_t b[2]) {
    asm volatile(
        "mma.sync.aligned.m16n8k8.row.col.f32.tf32.tf32.f32 "
        "{%0,%1,%2,%3}, {%4,%5,%6,%7}, {%8,%9}, {%0,%1,%2,%3};\n"
        : "+f"(d.x), "+f"(d.y), "+f"(d.z), "+f"(d.w)
        : "r"(a[0]), "r"(a[1]), "r"(a[2]), "r"(a[3]), "r"(b[0]), "r"(b[1]));
}

// 128x128 block tile MMA step over one staged BK=16 slice.
// 8 warps: warp_m = warp&3 (32-row stripes), warp_n = warp>>2 (64-col stripes).
__device__ __forceinline__ void mma_block(
    const uint32_t (*__restrict__ As)[136], const uint32_t (*__restrict__ Bs)[136],
    float4 acc[2][8], int warp_m, int warp_n, int g_, int t_)
{
#pragma unroll
    for (int ks = 0; ks < 2; ks++) {
        const int kb = ks * 8;
        uint32_t a[2][4], b[8][2];
#pragma unroll
        for (int mt = 0; mt < 2; mt++) {
            int rb = warp_m * 32 + mt * 16 + g_;
            a[mt][0] = As[kb + t_][rb];
            a[mt][1] = As[kb + t_][rb + 8];
            a[mt][2] = As[kb + t_ + 4][rb];
            a[mt][3] = As[kb + t_ + 4][rb + 8];
        }
#pragma unroll
        for (int nt = 0; nt < 8; nt++) {
            int cb = warp_n * 64 + nt * 8 + g_;
            b[nt][0] = Bs[kb + t_][cb];
            b[nt][1] = Bs[kb + t_ + 4][cb];
        }
#pragma unroll
        for (int mt = 0; mt < 2; mt++)
#pragma unroll
            for (int nt = 0; nt < 8; nt++) mma_tf32(acc[mt][nt], a[mt], b[nt]);
    }
}

// ---------------- init / copy / last-pos / compact ---------------------------
__global__ void k_init() {
    int i = blockIdx.x * blockDim.x + threadIdx.x;
    if (i < N_NODES) g_last_pos[i] = -1;
    if (i < 2 * N_NODES) { g_mx[i] = 0u; g_denom[i] = 0.f; }
    if (i == 0) g_count = 0;
}

__global__ void k_copy(const float4* __restrict__ mem, const float* __restrict__ lu) {
    int i = blockIdx.x * blockDim.x + threadIdx.x;
    if (i < N_NODES * (MEMD / 4)) ((float4*)g_mem_new)[i] = mem[i];
    if (i < N_NODES) g_lu_new[i] = lu[i];
}

__global__ void k_lastpos(const int* __restrict__ src, const int* __restrict__ dst) {
    int j = blockIdx.x * blockDim.x + threadIdx.x;
    if (j >= TWO_E) return;
    int id = (j < N_EVENTS) ? src[j] : dst[j - N_EVENTS];
    atomicMax(&g_last_pos[id], j);
}

__global__ void k_compact(const int* __restrict__ src, const int* __restrict__ dst) {
    int j = blockIdx.x * blockDim.x + threadIdx.x;
    if (j >= TWO_E) return;
    int id = (j < N_EVENTS) ? src[j] : dst[j - N_EVENTS];
    if (g_last_pos[id] == j) {
        int p = atomicAdd(&g_count, 1);
        g_sel[p] = j;
    }
}

// ---------------- time-enc precompute ----------------------------------------
__global__ void k_te_gru(const float* __restrict__ last_update, const float* __restrict__ t,
                         const int* __restrict__ src, const int* __restrict__ dst,
                         const float* __restrict__ time_w, const float* __restrict__ time_b)
{
    int i = blockIdx.x * blockDim.x + threadIdx.x;
    int m = i >> 6, j = i & 63;
    if (m >= g_count) return;
    int sel = g_sel[m];
    int e  = (sel < N_EVENTS) ? sel : sel - N_EVENTS;
    int id = (sel < N_EVENTS) ? src[e] : dst[e];
    float dt = t[e] - last_update[id];
    g_te[(size_t)m * 64 + j] = cosf(fmaf(dt, time_w[j], time_b[j]));
}

__global__ void k_te_edge(const float* __restrict__ t, const int* __restrict__ src,
                          const float* __restrict__ time_w, const float* __restrict__ time_b)
{
    int i = blockIdx.x * blockDim.x + threadIdx.x;
    if (i >= N_EVENTS * 64) return;
    int e = i >> 6, j = i & 63;
    float rt = g_lu_new[src[e]] - t[e];
    g_te2[i] = cosf(fmaf(rt, time_w[j], time_b[j]));
}

// ---------------- GRU GEMM (BM=128, BN=128, grid.y = gate group) --------------
// A(K=512 virtual) = [mem_id(128) | mem_oth(128) | msg(64) | te(64) | mem_id(128)]
// grp 0(r),1(z): K=[0,512); grp 2(i_n): K=[0,384); grp 3(h_n): K=[384,512)
__global__ __launch_bounds__(256) void k_gru_gemm(
    const float* __restrict__ memory,
    const int* __restrict__ src, const int* __restrict__ dst,
    const float* __restrict__ msg,
    const float* __restrict__ Wih, const float* __restrict__ Whh)
{
    const int count = g_count;
    const int m0 = blockIdx.x * 128;
    if (m0 >= count) return;
    const int grp = blockIdx.y;
    const int k_lo = (grp == 3) ? 384 : 0;
    const int k_hi = (grp == 2) ? 384 : 512;
    const int tid = threadIdx.x;
    const int lane = tid & 31, warp = tid >> 5;
    const int warp_m = warp & 3, warp_n = warp >> 2;
    const int g_ = lane >> 2, t_ = lane & 3;

    __shared__ int      s_id[128], s_oth[128], s_e[128];
    __shared__ uint32_t As[16][136];
    __shared__ uint32_t Bs[16][136];

    if (tid < 128) {
        int mm = min(m0 + tid, count - 1);
        int j = g_sel[mm];
        int e  = (j < N_EVENTS) ? j : j - N_EVENTS;
        s_id[tid]  = (j < N_EVENTS) ? src[e] : dst[e];
        s_oth[tid] = (j < N_EVENTS) ? dst[e] : src[e];
        s_e[tid] = e;
    }
    __syncthreads();

    float4 acc[2][8];
#pragma unroll
    for (int i = 0; i < 2; i++)
#pragma unroll
        for (int j = 0; j < 8; j++) acc[i][j] = make_float4(0.f, 0.f, 0.f, 0.f);

    for (int k0 = k_lo; k0 < k_hi; k0 += 16) {
#pragma unroll
        for (int s = 0; s < 8; s++) {
            int idx = tid + s * 256;
            int kk = idx & 15, m = idx >> 4;
            int k = k0 + kk;
            float v;
            if (k < 128)       v = memory[(size_t)s_id[m] * 128 + k];
            else if (k < 256)  v = memory[(size_t)s_oth[m] * 128 + (k - 128)];
            else if (k < 320)  v = msg[(size_t)s_e[m] * 64 + (k - 256)];
            else if (k < 384)  v = g_te[(size_t)min(m0 + m, count - 1) * 64 + (k - 320)];
            else               v = memory[(size_t)s_id[m] * 128 + (k - 384)];
            As[kk][m] = f2tf32(v);
        }
#pragma unroll
        for (int s = 0; s < 8; s++) {
            int idx = tid + s * 256;
            int kk = idx & 15, n = idx >> 4;
            int k = k0 + kk;
            float v;
            if (grp < 2)       v = (k < 384) ? Wih[(size_t)(grp * 128 + n) * 384 + k]
                                             : Whh[(size_t)(grp * 128 + n) * 128 + (k - 384)];
            else if (grp == 2) v = Wih[(size_t)(256 + n) * 384 + k];
            else               v = Whh[(size_t)(256 + n) * 128 + (k - 384)];
            Bs[kk][n] = f2tf32(v);
        }
        __syncthreads();
        mma_block(As, Bs, acc, warp_m, warp_n, g_, t_);
        __syncthreads();
    }
#pragma unroll
    for (int mt = 0; mt < 2; mt++)
#pragma unroll
        for (int nt = 0; nt < 8; nt++) {
            int r0 = m0 + warp_m * 32 + mt * 16 + g_;
            int c  = grp * 128 + warp_n * 64 + nt * 8 + 2 * t_;
            if (r0 < count)
                *(float2*)&g_G[(size_t)r0 * 512 + c] = make_float2(acc[mt][nt].x, acc[mt][nt].y);
            if (r0 + 8 < count)
                *(float2*)&g_G[(size_t)(r0 + 8) * 512 + c] = make_float2(acc[mt][nt].z, acc[mt][nt].w);
        }
}

// ---------------- GRU gates + scatter -----------------------------------------
__global__ void k_gates(const float* __restrict__ memory, const float* __restrict__ last_update,
                        const float* __restrict__ t,
                        const int* __restrict__ src, const int* __restrict__ dst,
                        const float* __restrict__ bih, const float* __restrict__ bhh)
{
    int m = blockIdx.x;
    if (m >= g_count) return;
    int j = g_sel[m];
    int e  = (j < N_EVENTS) ? j : j - N_EVENTS;
    int id = (j < N_EVENTS) ? src[e] : dst[e];
    int d = threadIdx.x;  // 128
    const float* G = &g_G[(size_t)m * 512];
    float g0 = G[d], g1 = G[128 + d], g2 = G[256 + d], g3 = G[384 + d];
    float h = memory[(size_t)id * 128 + d];
    float r = sigmoidf_(g0 + bih[d] + bhh[d]);
    float z = sigmoidf_(g1 + bih[128 + d] + bhh[128 + d]);
    float n = tanhf(g2 + bih[256 + d] + r * (g3 + bhh[256 + d]));
    g_mem_new[(size_t)id * 128 + d] = (1.f - z) * n + z * h;
    if (d == 0) g_lu_new[id] = fmaxf(last_update[id], t[e]);
}

// ---------------- per-edge k,v GEMM: [E x 256], BN=128, grid.y in {0,1} -------
__global__ __launch_bounds__(256) void k_kv_gemm(
    const float* __restrict__ msg, const int* __restrict__ src,
    const float* __restrict__ Wk, const float* __restrict__ bk,
    const float* __restrict__ Wv, const float* __restrict__ bv,
    const float* __restrict__ We)
{
    const int m0 = blockIdx.x * 128;
    const int bn0 = blockIdx.y * 128;
    const int tid = threadIdx.x;
    const int lane = tid & 31, warp = tid >> 5;
    const int warp_m = warp & 3, warp_n = warp >> 2;
    const int g_ = lane >> 2, t_ = lane & 3;

    __shared__ int      s_src[128], s_ec[128];
    __shared__ uint32_t As[16][136];
    __shared__ uint32_t Bs[16][136];

    if (tid < 128) {
        int e = min(m0 + tid, N_EVENTS - 1);
        s_src[tid] = src[e]; s_ec[tid] = e;
    }
    __syncthreads();

    float4 acc[2][8];
#pragma unroll
    for (int i = 0; i < 2; i++)
#pragma unroll
        for (int j = 0; j < 8; j++) acc[i][j] = make_float4(0.f, 0.f, 0.f, 0.f);

    for (int k0 = 0; k0 < 256; k0 += 16) {
#pragma unroll
        for (int s = 0; s < 8; s++) {
            int idx = tid + s * 256;
            int kk = idx & 15, m = idx >> 4;
            int k = k0 + kk;
            float v;
            if (k < 128)      v = g_mem_new[(size_t)s_src[m] * 128 + k];
            else if (k < 192) v = g_te2[(size_t)s_ec[m] * 64 + (k - 128)];
            else              v = msg[(size_t)s_ec[m] * 64 + (k - 192)];
            As[kk][m] = f2tf32(v);
        }
#pragma unroll
        for (int s = 0; s < 8; s++) {
            int idx = tid + s * 256;
            int kk = idx & 15, n = idx >> 4;
            int k = k0 + kk;
            int o = bn0 + n;
            float v;
            if (o < 128) v = (k < 128) ? Wk[(size_t)o * 128 + k] : We[(size_t)o * 128 + (k - 128)];
            else { int o2 = o - 128;
                   v = (k < 128) ? Wv[(size_t)o2 * 128 + k] : We[(size_t)o2 * 128 + (k - 128)]; }
            Bs[kk][n] = f2tf32(v);
        }
        __syncthreads();
        mma_block(As, Bs, acc, warp_m, warp_n, g_, t_);
        __syncthreads();
    }
#pragma unroll
    for (int mt = 0; mt < 2; mt++)
#pragma unroll
        for (int nt = 0; nt < 8; nt++) {
            int r0 = m0 + warp_m * 32 + mt * 16 + g_;
            int c  = bn0 + warp_n * 64 + nt * 8 + 2 * t_;
            float b0 = (c < 128) ? bk[c] : bv[c - 128];
            float b1 = (c + 1 < 128) ? bk[c + 1] : bv[c + 1 - 128];
            if (r0 < N_EVENTS)
                *(float2*)&g_kv[(size_t)r0 * 256 + c] =
                    make_float2(acc[mt][nt].x + b0, acc[mt][nt].y + b1);
            if (r0 + 8 < N_EVENTS)
                *(float2*)&g_kv[(size_t)(r0 + 8) * 256 + c] =
                    make_float2(acc[mt][nt].z + b0, acc[mt][nt].w + b1);
        }
}

// ---------------- q GEMM + fused logit dot + segment max ----------------------
__global__ __launch_bounds__(256) void k_q_logit(
    const int* __restrict__ dst,
    const float* __restrict__ Wq, const float* __restrict__ bq)
{
    const int m0 = blockIdx.x * 128;
    const int tid = threadIdx.x;
    const int lane = tid & 31, warp = tid >> 5;
    const int warp_m = warp & 3, warp_n = warp >> 2;
    const int g_ = lane >> 2, t_ = lane & 3;

    __shared__ int      s_dst[128];
    __shared__ uint32_t As[16][136];
    __shared__ uint32_t Bs[16][136];
    __shared__ float    logit_s[256];   // [row][head]

    if (tid < 128) s_dst[tid] = dst[min(m0 + tid, N_EVENTS - 1)];
    logit_s[tid] = 0.f;
    __syncthreads();

    float4 acc[2][8];
#pragma unroll
    for (int i = 0; i < 2; i++)
#pragma unroll
        for (int j = 0; j < 8; j++) acc[i][j] = make_float4(0.f, 0.f, 0.f, 0.f);

    for (int k0 = 0; k0 < 128; k0 += 16) {
#pragma unroll
        for (int s = 0; s < 8; s++) {
            int idx = tid + s * 256;
            int kk = idx & 15, m = idx >> 4;
            As[kk][m] = f2tf32(g_mem_new[(size_t)s_dst[m] * 128 + k0 + kk]);
        }
#pragma unroll
        for (int s = 0; s < 8; s++) {
            int idx = tid + s * 256;
            int kk = idx & 15, n = idx >> 4;
            Bs[kk][n] = f2tf32(Wq[(size_t)n * 128 + k0 + kk]);
        }
        __syncthreads();
        mma_block(As, Bs, acc, warp_m, warp_n, g_, t_);
        __syncthreads();
    }
    // epilogue: logit_partial[row][head] = sum_c (q_c + bq_c) * kv[row][c]
    // warp_n == head (cols [0,64) head0, [64,128) head1)
    float p[4] = {0.f, 0.f, 0.f, 0.f};   // [mt][lo/hi8]
#pragma unroll
    for (int mt = 0; mt < 2; mt++) {
        int r0 = m0 + warp_m * 32 + mt * 16 + g_;
        int r0c = min(r0, N_EVENTS - 1);
        int r1c = min(r0 + 8, N_EVENTS - 1);
#pragma unroll
        for (int nt = 0; nt < 8; nt++) {
            int c = warp_n * 64 + nt * 8 + 2 * t_;
            float bq0 = bq[c], bq1 = bq[c + 1];
            p[mt * 2 + 0] += (acc[mt][nt].x + bq0) * g_kv[(size_t)r0c * 256 + c]
                           + (acc[mt][nt].y + bq1) * g_kv[(size_t)r0c * 256 + c + 1];
            p[mt * 2 + 1] += (acc[mt][nt].z + bq0) * g_kv[(size_t)r1c * 256 + c]
                           + (acc[mt][nt].w + bq1) * g_kv[(size_t)r1c * 256 + c + 1];
        }
    }
#pragma unroll
    for (int mt = 0; mt < 2; mt++) {
        int rl = warp_m * 32 + mt * 16 + g_;
        atomicAdd(&logit_s[rl * 2 + warp_n], p[mt * 2 + 0]);
        atomicAdd(&logit_s[(rl + 8) * 2 + warp_n], p[mt * 2 + 1]);
    }
    __syncthreads();
    {
        int rl = tid >> 1, h = tid & 1;
        int m = m0 + rl;
        if (m < N_EVENTS) {
            float lg = logit_s[tid] * 0.125f;
            g_logit[m * 2 + h] = lg;
            atomicMax(&g_mx[(size_t)s_dst[rl] * 2 + h], enc_f(lg));
        }
    }
}

// ---------------- exp + denom --------------------------------------------------
__global__ void k_expsum(const int* __restrict__ dst) {
    int i = blockIdx.x * blockDim.x + threadIdx.x;
    if (i >= N_EVENTS * 2) return;
    int e = i >> 1, h = i & 1;
    int dn = dst[e];
    float mxv = dec_f(g_mx[dn * 2 + h]);
    float a = expf(g_logit[i] - mxv);
    g_aexp[i] = a;
    atomicAdd(&g_denom[dn * 2 + h], a);
}

// ---------------- skip GEMM: z = mem_new @ Wskip^T + bskip (BN=128) -----------
__global__ __launch_bounds__(256) void k_skip_gemm(
    const float* __restrict__ Wskip, const float* __restrict__ bskip)
{
    const int m0 = blockIdx.x * 128;
    const int tid = threadIdx.x;
    const int lane = tid & 31, warp = tid >> 5;
    const int warp_m = warp & 3, warp_n = warp >> 2;
    const int g_ = lane >> 2, t_ = lane & 3;

    __shared__ uint32_t As[16][136];
    __shared__ uint32_t Bs[16][136];

    float4 acc[2][8];
#pragma unroll
    for (int i = 0; i < 2; i++)
#pragma unroll
        for (int j = 0; j < 8; j++) acc[i][j] = make_float4(0.f, 0.f, 0.f, 0.f);

    for (int k0 = 0; k0 < 128; k0 += 16) {
#pragma unroll
        for (int s = 0; s < 8; s++) {
            int idx = tid + s * 256;
            int kk = idx & 15, m = idx >> 4;
            int mg = min(m0 + m, N_NODES - 1);
            As[kk][m] = f2tf32(g_mem_new[(size_t)mg * 128 + k0 + kk]);
        }
#pragma unroll
        for (int s = 0; s < 8; s++) {
            int idx = tid + s * 256;
            int kk = idx & 15, n = idx >> 4;
            Bs[kk][n] = f2tf32(Wskip[(size_t)n * 128 + k0 + kk]);
        }
        __syncthreads();
        mma_block(As, Bs, acc, warp_m, warp_n, g_, t_);
        __syncthreads();
    }
#pragma unroll
    for (int mt = 0; mt < 2; mt++)
#pragma unroll
        for (int nt = 0; nt < 8; nt++) {
            int r0 = m0 + warp_m * 32 + mt * 16 + g_;
            int c  = warp_n * 64 + nt * 8 + 2 * t_;
            float b0 = bskip[c], b1 = bskip[c + 1];
            if (r0 < N_NODES)
                *(float2*)&g_z[(size_t)r0 * 128 + c] =
                    make_float2(acc[mt][nt].x + b0, acc[mt][nt].y + b1);
            if (r0 + 8 < N_NODES)
                *(float2*)&g_z[(size_t)(r0 + 8) * 128 + c] =
                    make_float2(acc[mt][nt].z + b0, acc[mt][nt].w + b1);
        }
}

// ---------------- scatter attention output into z ------------------------------
__global__ void k_scatter(const int* __restrict__ dst) {
    int e = blockIdx.x;
    int d = threadIdx.x;          // 128
    int dn = dst[e];
    int h = d >> 6;
    float attn = g_aexp[e * 2 + h] / g_denom[dn * 2 + h];
    atomicAdd(&g_z[(size_t)dn * 128 + d], attn * g_kv[(size_t)e * 256 + 128 + d]);
}

// ---------------- link predictor: 3xTF32 GEMM + fused relu/Wlf reduction -------
__global__ __launch_bounds__(256) void k_linkpred(
    const int* __restrict__ src, const int* __restrict__ dst,
    const float* __restrict__ Wls, const float* __restrict__ bls,
    const float* __restrict__ Wld, const float* __restrict__ bld,
    const float* __restrict__ Wlf, const float* __restrict__ blf,
    float* __restrict__ out)
{
    const int m0 = blockIdx.x * 128;
    const int tid = threadIdx.x;
    const int lane = tid & 31, warp = tid >> 5;
    const int warp_m = warp & 3, warp_n = warp >> 2;
    const int g_ = lane >> 2, t_ = lane & 3;

    __shared__ int      s_src[128], s_dst[128];
    __shared__ uint32_t Ah[16][136], Al[16][136];
    __shared__ uint32_t Bh[16][136], Bl[16][136];
    __shared__ float    out_s[128];

    if (tid < 128) {
        int e = min(m0 + tid, N_EVENTS - 1);
        s_src[tid] = src[e];
        s_dst[tid] = dst[e];
        out_s[tid] = 0.f;
    }
    __syncthreads();

    float4 acc[2][8];
#pragma unroll
    for (int i = 0; i < 2; i++)
#pragma unroll
        for (int j = 0; j < 8; j++) acc[i][j] = make_float4(0.f, 0.f, 0.f, 0.f);

    for (int k0 = 0; k0 < 256; k0 += 16) {
#pragma unroll
        for (int s = 0; s < 8; s++) {
            int idx = tid + s * 256;
            int kk = idx & 15, m = idx >> 4;
            int k = k0 + kk;
            float v = (k < 128) ? g_z[(size_t)s_src[m] * 128 + k]
                                : g_z[(size_t)s_dst[m] * 128 + (k - 128)];
            uint32_t h = f2tf32(v);
            Ah[kk][m] = h;
            Al[kk][m] = f2tf32(v - __uint_as_float(h));
        }
#pragma unroll
        for (int s = 0; s < 8; s++) {
            int idx = tid + s * 256;
            int kk = idx & 15, n = idx >> 4;
            int k = k0 + kk;
            float v = (k < 128) ? Wls[(size_t)n * 128 + k] : Wld[(size_t)n * 128 + (k - 128)];
            uint32_t h = f2tf32(v);
            Bh[kk][n] = h;
            Bl[kk][n] = f2tf32(v - __uint_as_float(h));
        }
        __syncthreads();
        mma_block(Ah, Bl, acc, warp_m, warp_n, g_, t_);
        mma_block(Al, Bh, acc, warp_m, warp_n, g_, t_);
        mma_block(Ah, Bh, acc, warp_m, warp_n, g_, t_);
        __syncthreads();
    }
    // epilogue: relu(acc + bls + bld) dot Wlf, reduce per row
    float p[4] = {0.f, 0.f, 0.f, 0.f};
#pragma unroll
    for (int mt = 0; mt < 2; mt++) {
#pragma unroll
        for (int nt = 0; nt < 8; nt++) {
            int c = warp_n * 64 + nt * 8 + 2 * t_;
            float bb0 = bls[c] + bld[c], bb1 = bls[c + 1] + bld[c + 1];
            float w0 = Wlf[c], w1 = Wlf[c + 1];
            p[mt * 2 + 0] += fmaxf(acc[mt][nt].x + bb0, 0.f) * w0
                           + fmaxf(acc[mt][nt].y + bb1, 0.f) * w1;
            p[mt * 2 + 1] += fmaxf(acc[mt][nt].z + bb0, 0.f) * w0
                           + fmaxf(acc[mt][nt].w + bb1, 0.f) * w1;
        }
    }
#pragma unroll
    for (int mt = 0; mt < 2; mt++) {
        int rl = warp_m * 32 + mt * 16 + g_;
        atomicAdd(&out_s[rl], p[mt * 2 + 0]);
        atomicAdd(&out_s[rl + 8], p[mt * 2 + 1]);
    }
    __syncthreads();
    if (tid < 128 && m0 + tid < N_EVENTS)
        out[m0 + tid] = out_s[tid] + blf[0];
}

// ---------------- launch --------------------------------------------------------
extern "C" void kernel_launch(void* const* d_in, const int* in_sizes, int n_in,
                              void* d_out, int out_size)
{
    const float* memory      = (const float*)d_in[0];
    const float* last_update = (const float*)d_in[1];
    const float* t           = (const float*)d_in[2];
    const float* msg         = (const float*)d_in[3];
    const int*   src         = (const int*)d_in[4];
    const int*   dst         = (const int*)d_in[5];
    const float* time_w      = (const float*)d_in[6];
    const float* time_b      = (const float*)d_in[7];
    const float* gru_Wih     = (const float*)d_in[8];
    const float* gru_bih     = (const float*)d_in[9];
    const float* gru_Whh     = (const float*)d_in[10];
    const float* gru_bhh     = (const float*)d_in[11];
    const float* Wq          = (const float*)d_in[12];
    const float* bq          = (const float*)d_in[13];
    const float* Wk          = (const float*)d_in[14];
    const float* bk          = (const float*)d_in[15];
    const float* Wv          = (const float*)d_in[16];
    const float* bv          = (const float*)d_in[17];
    const float* We          = (const float*)d_in[18];
    const float* Wskip       = (const float*)d_in[19];
    const float* bskip       = (const float*)d_in[20];
    const float* Wls         = (const float*)d_in[21];
    const float* bls         = (const float*)d_in[22];
    const float* Wld         = (const float*)d_in[23];
    const float* bld         = (const float*)d_in[24];
    const float* Wlf         = (const float*)d_in[25];
    const float* blf         = (const float*)d_in[26];
    float* out = (float*)d_out;

    k_init<<<(2 * N_NODES + 255) / 256, 256>>>();
    k_copy<<<(N_NODES * (MEMD / 4) + 255) / 256, 256>>>((const float4*)memory, last_update);
    k_lastpos<<<(TWO_E + 255) / 256, 256>>>(src, dst);
    k_compact<<<(TWO_E + 255) / 256, 256>>>(src, dst);
    k_te_gru<<<(TWO_E * 64 + 255) / 256, 256>>>(last_update, t, src, dst, time_w, time_b);
    {
        dim3 grid((TWO_E + 127) / 128, 4);
        k_gru_gemm<<<grid, 256>>>(memory, src, dst, msg, gru_Wih, gru_Whh);
    }
    k_gates<<<TWO_E, 128>>>(memory, last_update, t, src, dst, gru_bih, gru_bhh);
    k_te_edge<<<(N_EVENTS * 64 + 255) / 256, 256>>>(t, src, time_w, time_b);
    {
        dim3 grid((N_EVENTS + 127) / 128, 2);
        k_kv_gemm<<<grid, 256>>>(msg, src, Wk, bk, Wv, bv, We);
    }
    k_q_logit<<<(N_EVENTS + 127) / 128, 256>>>(dst, Wq, bq);
    k_expsum<<<(N_EVENTS * 2 + 255) / 256, 256>>>(dst);
    k_skip_gemm<<<(N_NODES + 127) / 128, 256>>>(Wskip, bskip);
    k_scatter<<<N_EVENTS, 128>>>(dst);
    k_linkpred<<<(N_EVENTS + 127) / 128, 256>>>(src, dst, Wls, bls, Wld, bld, Wlf, blf, out);
}